// round 6
// baseline (speedup 1.0000x reference)
#include <cuda_runtime.h>
#include <math_constants.h>

// Problem constants
constexpr int B_ = 2;
constexpr int N_ = 2048;
constexpr int C_ = 1024;
constexpr int H_ = 16;
constexpr int D_ = 64;
constexpr int M_ = B_ * N_;      // 4096 rows of x
constexpr float SCALE = 0.125f;  // D^-0.5

// Scratch (device globals; no allocation allowed)
__device__ float g_q[(size_t)B_ * H_ * N_ * D_];   // [B*H, N, D] (tf32-rounded)
__device__ float g_k[(size_t)B_ * H_ * N_ * D_];
__device__ float g_v[(size_t)B_ * H_ * N_ * D_];
__device__ float g_ao[(size_t)B_ * N_ * C_];       // attn out [B*N, C] (tf32-rounded)
__device__ float g_xr[(size_t)M_ * C_];            // x rounded to tf32
__device__ float g_wqkv[(size_t)3 * C_ * C_];      // qkv_w rounded to tf32
__device__ float g_wproj[(size_t)C_ * C_];         // proj_w rounded to tf32

// ---------------------------------------------------------------------------
// helpers
// ---------------------------------------------------------------------------
__device__ __forceinline__ unsigned f2tf(float f) {
    unsigned u;
    asm("cvt.rna.tf32.f32 %0, %1;" : "=r"(u) : "f"(f));
    return u;
}
__device__ __forceinline__ float tf32r(float f) {
    return __uint_as_float(f2tf(f));
}

__device__ __forceinline__ void mma_tf32(
    float& c0, float& c1, float& c2, float& c3,
    unsigned a0, unsigned a1, unsigned a2, unsigned a3,
    unsigned b0, unsigned b1)
{
    asm volatile(
        "mma.sync.aligned.m16n8k8.row.col.f32.tf32.tf32.f32 "
        "{%0,%1,%2,%3}, {%4,%5,%6,%7}, {%8,%9}, {%0,%1,%2,%3};"
        : "+f"(c0), "+f"(c1), "+f"(c2), "+f"(c3)
        : "r"(a0), "r"(a1), "r"(a2), "r"(a3), "r"(b0), "r"(b1));
}

__device__ __forceinline__ void cp_async16(unsigned saddr, const void* gptr) {
    asm volatile("cp.async.ca.shared.global [%0], [%1], 16;"
                 :: "r"(saddr), "l"(gptr));
}
__device__ __forceinline__ void cp_commit() {
    asm volatile("cp.async.commit_group;");
}

// ---------------------------------------------------------------------------
// Pre-pass: round fp32 buffer to tf32 (RNA) into scratch.
// ---------------------------------------------------------------------------
__global__ __launch_bounds__(256) void round_kernel(
    const float4* __restrict__ src, float4* __restrict__ dst, int n4)
{
    const int i = blockIdx.x * 256 + threadIdx.x;
    if (i < n4) {
        float4 v = src[i];
        v.x = tf32r(v.x); v.y = tf32r(v.y);
        v.z = tf32r(v.z); v.w = tf32r(v.w);
        dst[i] = v;
    }
}

// ---------------------------------------------------------------------------
// Unified tf32 TN GEMM on pre-rounded data: C = A @ W^T, K = 1024.
// Block 128x128x16, 8 warps (2x4), warp tile 64x32.
// 2-stage cp.async pipeline; raw bits are already tf32-rounded.
// EPI=0: qkv + RoPE scatter (rounds outputs).  EPI=1: bias add -> out.
// ---------------------------------------------------------------------------
constexpr int SA = 20;  // smem row stride (16 + 4 pad): conflict-free frags

template<int EPI>
__global__ __launch_bounds__(256) void gemm_tf32_kernel(
    const float* __restrict__ fcos, const float* __restrict__ fsin,
    const float* __restrict__ bias, float* __restrict__ out)
{
    __shared__ float As[2][128 * SA];
    __shared__ float Bs[2][128 * SA];

    const float* A = (EPI == 1) ? g_ao : g_xr;
    const float* W = (EPI == 1) ? g_wproj : g_wqkv;

    const int tid = threadIdx.x;
    const int w = tid >> 5;
    const int lane = tid & 31;
    const int g = lane >> 2;     // 0..7
    const int t = lane & 3;      // 0..3
    const int wm = w >> 2;       // 0..1
    const int wn = w & 3;        // 0..3

    const int m0 = blockIdx.y * 128;
    const int n0 = blockIdx.x * 128;

    const int r0 = tid >> 2;           // 0..63
    const int c4 = (tid & 3) * 4;      // 0,4,8,12

    const float* ag0 = A + (size_t)(m0 + r0) * 1024 + c4;
    const float* ag1 = ag0 + (size_t)64 * 1024;
    const float* bg0 = W + (size_t)(n0 + r0) * 1024 + c4;
    const float* bg1 = bg0 + (size_t)64 * 1024;

    const unsigned sa0 = (unsigned)__cvta_generic_to_shared(&As[0][r0 * SA + c4]);
    const unsigned sa1 = (unsigned)__cvta_generic_to_shared(&As[0][(r0 + 64) * SA + c4]);
    const unsigned sb0 = (unsigned)__cvta_generic_to_shared(&Bs[0][r0 * SA + c4]);
    const unsigned sb1 = (unsigned)__cvta_generic_to_shared(&Bs[0][(r0 + 64) * SA + c4]);
    const unsigned stg = 128 * SA * 4;   // bytes per stage buffer

    float acc[4][4][4];
#pragma unroll
    for (int i = 0; i < 4; i++)
#pragma unroll
        for (int j = 0; j < 4; j++)
#pragma unroll
            for (int q = 0; q < 4; q++) acc[i][j][q] = 0.f;

    // prologue: stage 0
    cp_async16(sa0, ag0);
    cp_async16(sa1, ag1);
    cp_async16(sb0, bg0);
    cp_async16(sb1, bg1);
    cp_commit();

    for (int kt = 0; kt < 64; kt++) {
        const int buf = kt & 1;
        __syncthreads();   // WAR: all done with buffer buf^1
        if (kt < 63) {
            const int k0 = (kt + 1) * 16;
            const unsigned so = (unsigned)((kt + 1) & 1) * stg;
            cp_async16(sa0 + so, ag0 + k0);
            cp_async16(sa1 + so, ag1 + k0);
            cp_async16(sb0 + so, bg0 + k0);
            cp_async16(sb1 + so, bg1 + k0);
            cp_commit();
            asm volatile("cp.async.wait_group 1;");
        } else {
            asm volatile("cp.async.wait_group 0;");
        }
        __syncthreads();   // stage kt visible

#pragma unroll
        for (int ks = 0; ks < 2; ks++) {
            unsigned afr[4][4];
#pragma unroll
            for (int i = 0; i < 4; i++) {
                const float* p =
                    &As[buf][(wm * 64 + i * 16 + g) * SA + ks * 8 + t];
                afr[i][0] = __float_as_uint(p[0]);
                afr[i][1] = __float_as_uint(p[8 * SA]);
                afr[i][2] = __float_as_uint(p[4]);
                afr[i][3] = __float_as_uint(p[8 * SA + 4]);
            }
            unsigned bfr[4][2];
#pragma unroll
            for (int j = 0; j < 4; j++) {
                const float* p =
                    &Bs[buf][(wn * 32 + j * 8 + g) * SA + ks * 8 + t];
                bfr[j][0] = __float_as_uint(p[0]);
                bfr[j][1] = __float_as_uint(p[4]);
            }
#pragma unroll
            for (int i = 0; i < 4; i++)
#pragma unroll
                for (int j = 0; j < 4; j++)
                    mma_tf32(acc[i][j][0], acc[i][j][1], acc[i][j][2], acc[i][j][3],
                             afr[i][0], afr[i][1], afr[i][2], afr[i][3],
                             bfr[j][0], bfr[j][1]);
        }
    }

    // Epilogue: thread holds cols (2t,2t+1) of rows (g, g+8) per tile.
#pragma unroll
    for (int i = 0; i < 4; i++) {
        const int mlo = m0 + wm * 64 + i * 16 + g;
#pragma unroll
        for (int j = 0; j < 4; j++) {
            const int col = n0 + wn * 32 + j * 8 + 2 * t;  // even
            if (EPI == 1) {
                const float2 bb = *(const float2*)&bias[col];
                float2 o0 = {acc[i][j][0] + bb.x, acc[i][j][1] + bb.y};
                float2 o1 = {acc[i][j][2] + bb.x, acc[i][j][3] + bb.y};
                *(float2*)&out[(size_t)mlo * 1024 + col] = o0;
                *(float2*)&out[(size_t)(mlo + 8) * 1024 + col] = o1;
            } else {
                const int part = col >> 10;            // 0=q 1=k 2=v
                const int h = (col >> 6) & (H_ - 1);
                const int d = col & (D_ - 1);          // even
                const int f = d >> 1;
#pragma unroll
                for (int rr = 0; rr < 2; rr++) {
                    const int m = mlo + rr * 8;
                    const int b = m >> 11;
                    const int nr = m & (N_ - 1);
                    const float v0 = acc[i][j][rr * 2 + 0];
                    const float v1 = acc[i][j][rr * 2 + 1];
                    const size_t off =
                        (((size_t)(b * H_ + h) * N_) + nr) * D_ + d;
                    if (part == 2) {
                        float2 o = {tf32r(v0), tf32r(v1)};
                        *(float2*)&g_v[off] = o;
                    } else {
                        const float c = fcos[nr * 32 + f];
                        const float s = fsin[nr * 32 + f];
                        float2 o = {tf32r(v0 * c - v1 * s),
                                    tf32r(v0 * s + v1 * c)};
                        float* dst = (part == 0) ? g_q : g_k;
                        *(float2*)&dst[off] = o;
                    }
                }
            }
        }
    }
}

// ---------------------------------------------------------------------------
// Kernel 2: tf32 tensor-core flash attention (inputs pre-rounded).
// Block: 128 queries x one (b,h). 8 warps, warp = m16 slab x full 64-key tile.
// ---------------------------------------------------------------------------
constexpr int SK = 68;  // smem stride (64 + 4): conflict-free B-frag LDS

__global__ __launch_bounds__(256) void attn_tc_kernel()
{
    __shared__ float Ks[64 * SK];  // K[key][d]
    __shared__ float Vt[64 * SK];  // V^T[d][key]

    const int tid = threadIdx.x;
    const int w = tid >> 5;
    const int lane = tid & 31;
    const int g = lane >> 2;
    const int t = lane & 3;

    const int bh = blockIdx.y;
    const int q0 = blockIdx.x * 128;
    const int qlo = q0 + w * 16 + g;      // row g of this warp's m16 slab

    const float* qb = g_q + (size_t)bh * N_ * D_;
    const float* kb = g_k + (size_t)bh * N_ * D_;
    const float* vb = g_v + (size_t)bh * N_ * D_;

    // Q A-fragments, pre-scaled (x0.125 is exact), register-resident.
    unsigned qf[8][4];
#pragma unroll
    for (int s = 0; s < 8; s++) {
        const float* plo = qb + (size_t)qlo * D_ + s * 8 + t;
        const float* phi = plo + 8 * D_;
        qf[s][0] = __float_as_uint(plo[0] * SCALE);
        qf[s][1] = __float_as_uint(phi[0] * SCALE);
        qf[s][2] = __float_as_uint(plo[4] * SCALE);
        qf[s][3] = __float_as_uint(phi[4] * SCALE);
    }

    float oacc[8][4];
#pragma unroll
    for (int j = 0; j < 8; j++)
#pragma unroll
        for (int q = 0; q < 4; q++) oacc[j][q] = 0.f;
    float m_lo = -CUDART_INF_F, m_hi = -CUDART_INF_F;
    float l_lo = 0.f, l_hi = 0.f;

    const int r0 = tid >> 2;           // 0..63
    const int c4 = (tid & 3) * 4;      // 0,4,8,12
    const int src_lo = (lane & 28) | (t >> 1);
    const int src_hi = src_lo + 2;
    const bool odd = t & 1;

    for (int kt = 0; kt < N_; kt += 64) {
        __syncthreads();  // prior tile's LDS reads done before overwrite
#pragma unroll
        for (int ch = 0; ch < 4; ch++) {
            const int c = c4 + ch * 16;
            float4 kv = *(const float4*)(kb + (size_t)(kt + r0) * D_ + c);
            *(float4*)&Ks[r0 * SK + c] = kv;
            float4 vv = *(const float4*)(vb + (size_t)(kt + r0) * D_ + c);
            Vt[(c + 0) * SK + r0] = vv.x;
            Vt[(c + 1) * SK + r0] = vv.y;
            Vt[(c + 2) * SK + r0] = vv.z;
            Vt[(c + 3) * SK + r0] = vv.w;
        }
        __syncthreads();

        // S = Q @ K^T : m16 x n64(keys) x k64(d)
        float sacc[8][4];
#pragma unroll
        for (int j = 0; j < 8; j++)
#pragma unroll
            for (int q = 0; q < 4; q++) sacc[j][q] = 0.f;
#pragma unroll
        for (int s = 0; s < 8; s++) {
#pragma unroll
            for (int j = 0; j < 8; j++) {
                const float* p = &Ks[(j * 8 + g) * SK + s * 8 + t];
                mma_tf32(sacc[j][0], sacc[j][1], sacc[j][2], sacc[j][3],
                         qf[s][0], qf[s][1], qf[s][2], qf[s][3],
                         __float_as_uint(p[0]), __float_as_uint(p[4]));
            }
        }

        // Online softmax. Rows: g -> elems {0,1}; g+8 -> elems {2,3}.
        float mx_lo = -CUDART_INF_F, mx_hi = -CUDART_INF_F;
#pragma unroll
        for (int j = 0; j < 8; j++) {
            mx_lo = fmaxf(mx_lo, fmaxf(sacc[j][0], sacc[j][1]));
            mx_hi = fmaxf(mx_hi, fmaxf(sacc[j][2], sacc[j][3]));
        }
#pragma unroll
        for (int off = 2; off >= 1; off >>= 1) {
            mx_lo = fmaxf(mx_lo, __shfl_xor_sync(0xffffffffu, mx_lo, off));
            mx_hi = fmaxf(mx_hi, __shfl_xor_sync(0xffffffffu, mx_hi, off));
        }
        const float mn_lo = fmaxf(m_lo, mx_lo);
        const float mn_hi = fmaxf(m_hi, mx_hi);
        const float al_lo = __expf(m_lo - mn_lo);
        const float al_hi = __expf(m_hi - mn_hi);
        float rs_lo = 0.f, rs_hi = 0.f;
#pragma unroll
        for (int j = 0; j < 8; j++) {
            sacc[j][0] = __expf(sacc[j][0] - mn_lo);
            sacc[j][1] = __expf(sacc[j][1] - mn_lo);
            sacc[j][2] = __expf(sacc[j][2] - mn_hi);
            sacc[j][3] = __expf(sacc[j][3] - mn_hi);
            rs_lo += sacc[j][0] + sacc[j][1];
            rs_hi += sacc[j][2] + sacc[j][3];
        }
#pragma unroll
        for (int off = 2; off >= 1; off >>= 1) {
            rs_lo += __shfl_xor_sync(0xffffffffu, rs_lo, off);
            rs_hi += __shfl_xor_sync(0xffffffffu, rs_hi, off);
        }
        l_lo = l_lo * al_lo + rs_lo;  m_lo = mn_lo;
        l_hi = l_hi * al_hi + rs_hi;  m_hi = mn_hi;
#pragma unroll
        for (int j = 0; j < 8; j++) {
            oacc[j][0] *= al_lo; oacc[j][1] *= al_lo;
            oacc[j][2] *= al_hi; oacc[j][3] *= al_hi;
        }

        // O += P @ V : per k-step s, build P A-frag (RNA-rounded) via shfl.
#pragma unroll
        for (int s = 0; s < 8; s++) {
            const float x0 = __shfl_sync(0xffffffffu, sacc[s][0], src_lo);
            const float x1 = __shfl_sync(0xffffffffu, sacc[s][1], src_lo);
            const float x2 = __shfl_sync(0xffffffffu, sacc[s][2], src_lo);
            const float x3 = __shfl_sync(0xffffffffu, sacc[s][3], src_lo);
            const float y0 = __shfl_sync(0xffffffffu, sacc[s][0], src_hi);
            const float y1 = __shfl_sync(0xffffffffu, sacc[s][1], src_hi);
            const float y2 = __shfl_sync(0xffffffffu, sacc[s][2], src_hi);
            const float y3 = __shfl_sync(0xffffffffu, sacc[s][3], src_hi);
            const unsigned a0 = f2tf(odd ? x1 : x0);
            const unsigned a1 = f2tf(odd ? x3 : x2);
            const unsigned a2 = f2tf(odd ? y1 : y0);
            const unsigned a3 = f2tf(odd ? y3 : y2);
#pragma unroll
            for (int jd = 0; jd < 8; jd++) {
                const float* p = &Vt[(jd * 8 + g) * SK + s * 8 + t];
                mma_tf32(oacc[jd][0], oacc[jd][1], oacc[jd][2], oacc[jd][3],
                         a0, a1, a2, a3,
                         __float_as_uint(p[0]), __float_as_uint(p[4]));
            }
        }
    }

    // Normalize and write to g_ao [B*N, C], tf32-rounded for proj GEMM.
    const float inv_lo = 1.0f / l_lo;
    const float inv_hi = 1.0f / l_hi;
    const int b = bh >> 4;
    const int h = bh & (H_ - 1);
#pragma unroll
    for (int jd = 0; jd < 8; jd++) {
        const int col = h * D_ + jd * 8 + 2 * t;
        float2 o0 = {tf32r(oacc[jd][0] * inv_lo), tf32r(oacc[jd][1] * inv_lo)};
        float2 o1 = {tf32r(oacc[jd][2] * inv_hi), tf32r(oacc[jd][3] * inv_hi)};
        *(float2*)&g_ao[((size_t)(b * N_ + qlo)) * C_ + col] = o0;
        *(float2*)&g_ao[((size_t)(b * N_ + qlo + 8)) * C_ + col] = o1;
    }
}

// ---------------------------------------------------------------------------
extern "C" void kernel_launch(void* const* d_in, const int* in_sizes, int n_in,
                              void* d_out, int out_size)
{
    (void)in_sizes; (void)n_in; (void)out_size;
    const float* x      = (const float*)d_in[0];
    const float* qkv_w  = (const float*)d_in[1];
    const float* proj_w = (const float*)d_in[2];
    const float* proj_b = (const float*)d_in[3];
    const float* fcos   = (const float*)d_in[4];
    const float* fsin   = (const float*)d_in[5];
    float* out = (float*)d_out;

    float* xr = nullptr;  float* wq = nullptr;  float* wp = nullptr;
    cudaGetSymbolAddress((void**)&xr, g_xr);
    cudaGetSymbolAddress((void**)&wq, g_wqkv);
    cudaGetSymbolAddress((void**)&wp, g_wproj);

    // 0) Pre-round inputs/weights to tf32 (RNA) once per call.
    {
        const int n4x = M_ * C_ / 4;          // 1M float4
        const int n4q = 3 * C_ * C_ / 4;      // 768K float4
        const int n4p = C_ * C_ / 4;          // 256K float4
        round_kernel<<<(n4x + 255) / 256, 256>>>((const float4*)x, (float4*)xr, n4x);
        round_kernel<<<(n4q + 255) / 256, 256>>>((const float4*)qkv_w, (float4*)wq, n4q);
        round_kernel<<<(n4p + 255) / 256, 256>>>((const float4*)proj_w, (float4*)wp, n4p);
    }

    // 1) QKV GEMM (tf32, cp.async, pre-rounded) + RoPE scatter
    gemm_tf32_kernel<0><<<dim3(3 * C_ / 128, M_ / 128), 256>>>(
        fcos, fsin, nullptr, nullptr);
    // 2) Flash attention (tf32 tensor cores, pre-rounded)
    attn_tc_kernel<<<dim3(N_ / 128, B_ * H_), 256>>>();
    // 3) Output projection (tf32, cp.async) + bias
    gemm_tf32_kernel<1><<<dim3(C_ / 128, M_ / 128), 256>>>(
        nullptr, nullptr, proj_b, out);
}